// round 1
// baseline (speedup 1.0000x reference)
#include <cuda_runtime.h>
#include <cuda_bf16.h>
#include <math.h>

// Problem constants
#define SEQ    2048
#define DIN    4096
#define DOUT   4096
#define NH     32
#define NKV    8
#define HD     128
#define GROUP  4

// Scratch buffers (allocation-free rule: use __device__ globals)
__device__ float g_Q[SEQ * DOUT];          // 32 MB
__device__ float g_K[SEQ * (NKV * HD)];    // 8 MB
__device__ float g_V[SEQ * (NKV * HD)];    // 8 MB
__device__ float g_ctx[SEQ * DOUT];        // 32 MB

// ---------------------------------------------------------------------------
// SGEMM: C[M,N] = A[M,K] @ B[N,K]^T   (both row-major, "NT" layout)
// 128x128 block tile, BK=8, 256 threads, 8x8 per-thread micro-tile.
// ---------------------------------------------------------------------------
__global__ __launch_bounds__(256) void sgemm_nt(
    const float* __restrict__ A, const float* __restrict__ B,
    float* __restrict__ C, int M, int N, int K)
{
    __shared__ float As[8][128];
    __shared__ float Bs[8][128];

    const int tid = threadIdx.x;
    const int bm = blockIdx.y * 128;
    const int bn = blockIdx.x * 128;
    const int tx = tid & 15;   // 0..15
    const int ty = tid >> 4;   // 0..15
    const int lr = tid >> 1;        // 0..127 (tile row for loads)
    const int lc = (tid & 1) * 4;   // 0 or 4

    const float* Ap = A + (size_t)(bm + lr) * K + lc;
    const float* Bp = B + (size_t)(bn + lr) * K + lc;

    float acc[8][8];
#pragma unroll
    for (int i = 0; i < 8; i++)
#pragma unroll
        for (int j = 0; j < 8; j++) acc[i][j] = 0.f;

    for (int k0 = 0; k0 < K; k0 += 8) {
        float4 a4 = *(const float4*)(Ap + k0);
        float4 b4 = *(const float4*)(Bp + k0);
        As[lc + 0][lr] = a4.x; As[lc + 1][lr] = a4.y;
        As[lc + 2][lr] = a4.z; As[lc + 3][lr] = a4.w;
        Bs[lc + 0][lr] = b4.x; Bs[lc + 1][lr] = b4.y;
        Bs[lc + 2][lr] = b4.z; Bs[lc + 3][lr] = b4.w;
        __syncthreads();

#pragma unroll
        for (int kk = 0; kk < 8; kk++) {
            float4 a0 = *(const float4*)(&As[kk][ty * 8]);
            float4 a1 = *(const float4*)(&As[kk][ty * 8 + 4]);
            float4 b0 = *(const float4*)(&Bs[kk][tx * 8]);
            float4 b1 = *(const float4*)(&Bs[kk][tx * 8 + 4]);
            float a[8] = {a0.x, a0.y, a0.z, a0.w, a1.x, a1.y, a1.z, a1.w};
            float b[8] = {b0.x, b0.y, b0.z, b0.w, b1.x, b1.y, b1.z, b1.w};
#pragma unroll
            for (int i = 0; i < 8; i++)
#pragma unroll
                for (int j = 0; j < 8; j++)
                    acc[i][j] = fmaf(a[i], b[j], acc[i][j]);
        }
        __syncthreads();
    }

#pragma unroll
    for (int i = 0; i < 8; i++) {
        float* Crow = C + (size_t)(bm + ty * 8 + i) * N + bn + tx * 8;
#pragma unroll
        for (int j = 0; j < 8; j++) Crow[j] = acc[i][j];
    }
}

// ---------------------------------------------------------------------------
// RoPE (in place) on a [SEQ, H*128] row-major tensor.
// out[d]    = x1*cos[d]    - x2*sin[d]
// out[d+64] = x2*cos[d+64] + x1*sin[d+64]
// ---------------------------------------------------------------------------
__global__ __launch_bounds__(256) void rope_kernel(
    float* __restrict__ T, const float* __restrict__ cosT,
    const float* __restrict__ sinT, int H)
{
    int idx = blockIdx.x * blockDim.x + threadIdx.x;
    int total = SEQ * H * 64;
    if (idx >= total) return;
    int d = idx & 63;
    int h = (idx >> 6) % H;
    int s = idx / (64 * H);

    float* row = T + (size_t)s * (H * HD) + h * HD;
    float x1 = row[d];
    float x2 = row[d + 64];
    float c1 = cosT[s * HD + d],      s1 = sinT[s * HD + d];
    float c2 = cosT[s * HD + d + 64], s2 = sinT[s * HD + d + 64];
    row[d]      = fmaf(x1, c1, -x2 * s1);
    row[d + 64] = fmaf(x2, c2,  x1 * s2);
}

// ---------------------------------------------------------------------------
// Flash attention (causal, GQA). One CTA = (64 q-rows) x (one head).
// BQ=64, BKV=64, fp32, online softmax. 256 threads.
// Smem: Qs[64][132], Kt[128][68] (K transposed), Vs[64][132], Ss[64][65],
//       m/l/alpha rows.
// ---------------------------------------------------------------------------
#define BQ  64
#define BKV 64
#define QPAD 132
#define KPAD 68
#define SPAD 65

__global__ __launch_bounds__(256) void attn_kernel(
    const float* __restrict__ Q, const float* __restrict__ K,
    const float* __restrict__ V, float* __restrict__ ctx)
{
    const int qb  = blockIdx.x;   // 0..31
    const int h   = blockIdx.y;   // 0..31
    const int hk  = h >> 2;       // GQA: kv head
    const int tid = threadIdx.x;
    const int tx  = tid & 15;
    const int ty  = tid >> 4;

    extern __shared__ float sm[];
    float* Qs   = sm;                       // [64][132]
    float* Kt   = Qs + BQ * QPAD;           // [128][68]
    float* Vs   = Kt + HD * KPAD;           // [64][132]
    float* Ss   = Vs + BKV * QPAD;          // [64][65]
    float* mrow = Ss + BQ * SPAD;           // [64]
    float* lrow = mrow + BQ;                // [64]
    float* arow = lrow + BQ;                // [64]

    const float scale = 0.08838834764831845f;  // 1/sqrt(128)

    // Load Q tile (pre-scaled)
#pragma unroll
    for (int i = 0; i < 8; i++) {
        int e  = tid + i * 256;
        int r  = e >> 5;
        int c4 = e & 31;
        float4 q4 = *(const float4*)(Q + (size_t)(qb * BQ + r) * DOUT + h * HD + c4 * 4);
        float* dst = Qs + r * QPAD + c4 * 4;
        dst[0] = q4.x * scale; dst[1] = q4.y * scale;
        dst[2] = q4.z * scale; dst[3] = q4.w * scale;
    }
    if (tid < BQ) { mrow[tid] = -1e30f; lrow[tid] = 0.f; }

    float accO[4][8];
#pragma unroll
    for (int i = 0; i < 4; i++)
#pragma unroll
        for (int j = 0; j < 8; j++) accO[i][j] = 0.f;

    for (int kb = 0; kb <= qb; kb++) {
        __syncthreads();  // previous iteration done with Kt/Vs/Ss

        // Load K transposed: Kt[d][r]
#pragma unroll
        for (int i = 0; i < 32; i++) {
            int e = tid + i * 256;
            int r = e & 63;
            int c = e >> 6;
            Kt[c * KPAD + r] = K[(size_t)(kb * BKV + r) * (NKV * HD) + hk * HD + c];
        }
        // Load V row-major padded
#pragma unroll
        for (int i = 0; i < 8; i++) {
            int e  = tid + i * 256;
            int r  = e >> 5;
            int c4 = e & 31;
            float4 v4 = *(const float4*)(V + (size_t)(kb * BKV + r) * (NKV * HD) + hk * HD + c4 * 4);
            float* dst = Vs + r * QPAD + c4 * 4;
            dst[0] = v4.x; dst[1] = v4.y; dst[2] = v4.z; dst[3] = v4.w;
        }
        __syncthreads();

        // S = Q @ K^T  (thread computes 4x4)
        float accS[4][4];
#pragma unroll
        for (int i = 0; i < 4; i++)
#pragma unroll
            for (int j = 0; j < 4; j++) accS[i][j] = 0.f;

        for (int d = 0; d < HD; d++) {
            float a[4], b[4];
#pragma unroll
            for (int i = 0; i < 4; i++) a[i] = Qs[(ty * 4 + i) * QPAD + d];
#pragma unroll
            for (int j = 0; j < 4; j++) b[j] = Kt[d * KPAD + tx * 4 + j];
#pragma unroll
            for (int i = 0; i < 4; i++)
#pragma unroll
                for (int j = 0; j < 4; j++)
                    accS[i][j] = fmaf(a[i], b[j], accS[i][j]);
        }

        const bool diag = (kb == qb);
#pragma unroll
        for (int i = 0; i < 4; i++) {
            int qg = qb * BQ + ty * 4 + i;
#pragma unroll
            for (int j = 0; j < 4; j++) {
                int kg = kb * BKV + tx * 4 + j;
                float v = accS[i][j];
                if (diag && kg > qg) v = -1e30f;
                Ss[(ty * 4 + i) * SPAD + tx * 4 + j] = v;
            }
        }
        __syncthreads();

        // Online softmax: 4 threads per row, 16 cols each
        {
            int row = tid >> 2;
            int seg = tid & 3;
            float lm = -1e30f;
#pragma unroll
            for (int c = 0; c < 16; c++)
                lm = fmaxf(lm, Ss[row * SPAD + seg * 16 + c]);
            lm = fmaxf(lm, __shfl_xor_sync(0xffffffffu, lm, 1));
            lm = fmaxf(lm, __shfl_xor_sync(0xffffffffu, lm, 2));
            float mold = mrow[row];
            float mnew = fmaxf(mold, lm);
            float alpha = __expf(mold - mnew);
            float ls = 0.f;
#pragma unroll
            for (int c = 0; c < 16; c++) {
                float p = __expf(Ss[row * SPAD + seg * 16 + c] - mnew);
                Ss[row * SPAD + seg * 16 + c] = p;
                ls += p;
            }
            ls += __shfl_xor_sync(0xffffffffu, ls, 1);
            ls += __shfl_xor_sync(0xffffffffu, ls, 2);
            if (seg == 0) {
                mrow[row] = mnew;
                lrow[row] = lrow[row] * alpha + ls;
                arow[row] = alpha;
            }
        }
        __syncthreads();

        // O = O*alpha + P @ V  (thread computes 4 rows x 8 cols)
        float al[4];
#pragma unroll
        for (int i = 0; i < 4; i++) al[i] = arow[ty * 4 + i];
#pragma unroll
        for (int i = 0; i < 4; i++)
#pragma unroll
            for (int j = 0; j < 8; j++) accO[i][j] *= al[i];

        for (int k = 0; k < BKV; k++) {
            float p[4];
#pragma unroll
            for (int i = 0; i < 4; i++) p[i] = Ss[(ty * 4 + i) * SPAD + k];
            float4 v0 = *(const float4*)(Vs + k * QPAD + tx * 8);
            float4 v1 = *(const float4*)(Vs + k * QPAD + tx * 8 + 4);
            float vv[8] = {v0.x, v0.y, v0.z, v0.w, v1.x, v1.y, v1.z, v1.w};
#pragma unroll
            for (int i = 0; i < 4; i++)
#pragma unroll
                for (int j = 0; j < 8; j++)
                    accO[i][j] = fmaf(p[i], vv[j], accO[i][j]);
        }
    }

    // Final normalize + store (lrow already synced before last PV phase)
    float linv[4];
#pragma unroll
    for (int i = 0; i < 4; i++) linv[i] = 1.f / lrow[ty * 4 + i];
#pragma unroll
    for (int i = 0; i < 4; i++) {
        int r = qb * BQ + ty * 4 + i;
        float* dst = ctx + (size_t)r * DOUT + h * HD + tx * 8;
#pragma unroll
        for (int j = 0; j < 8; j++) dst[j] = accO[i][j] * linv[i];
    }
}

// ---------------------------------------------------------------------------
// Launch
// ---------------------------------------------------------------------------
extern "C" void kernel_launch(void* const* d_in, const int* in_sizes, int n_in,
                              void* d_out, int out_size)
{
    const float* x    = (const float*)d_in[0];
    const float* cosT = (const float*)d_in[1];
    const float* sinT = (const float*)d_in[2];
    const float* Wq   = (const float*)d_in[3];
    const float* Wk   = (const float*)d_in[4];
    const float* Wv   = (const float*)d_in[5];
    const float* Wo   = (const float*)d_in[6];
    float* out = (float*)d_out;

    float *Qp, *Kp, *Vp, *Cp;
    cudaGetSymbolAddress((void**)&Qp, g_Q);
    cudaGetSymbolAddress((void**)&Kp, g_K);
    cudaGetSymbolAddress((void**)&Vp, g_V);
    cudaGetSymbolAddress((void**)&Cp, g_ctx);

    // Attention smem opt-in (immediate API; capture-safe)
    const int ATTN_SMEM = (BQ * QPAD + HD * KPAD + BKV * QPAD + BQ * SPAD + 3 * BQ) * 4;
    cudaFuncSetAttribute(attn_kernel, cudaFuncAttributeMaxDynamicSharedMemorySize, ATTN_SMEM);

    // Projections
    sgemm_nt<<<dim3(DOUT / 128, SEQ / 128), 256>>>(x, Wq, Qp, SEQ, DOUT, DIN);
    sgemm_nt<<<dim3((NKV * HD) / 128, SEQ / 128), 256>>>(x, Wk, Kp, SEQ, NKV * HD, DIN);
    sgemm_nt<<<dim3((NKV * HD) / 128, SEQ / 128), 256>>>(x, Wv, Vp, SEQ, NKV * HD, DIN);

    // RoPE on Q and K
    {
        int totQ = SEQ * NH * 64;
        rope_kernel<<<(totQ + 255) / 256, 256>>>(Qp, cosT, sinT, NH);
        int totK = SEQ * NKV * 64;
        rope_kernel<<<(totK + 255) / 256, 256>>>(Kp, cosT, sinT, NKV);
    }

    // Flash attention
    attn_kernel<<<dim3(SEQ / BQ, NH), 256, ATTN_SMEM>>>(Qp, Kp, Vp, Cp);

    // Output projection
    sgemm_nt<<<dim3(DOUT / 128, SEQ / 128), 256>>>(Cp, Wo, out, SEQ, DOUT, DIN);
}

// round 2
// speedup vs baseline: 2.1398x; 2.1398x over previous
#include <cuda_runtime.h>
#include <cuda_bf16.h>
#include <math.h>
#include <stdint.h>

// Problem constants
#define SEQ    2048
#define DIN    4096
#define DOUT   4096
#define NH     32
#define NKV    8
#define HD     128
#define GROUP  4

// Scratch buffers (allocation-free rule: use __device__ globals)
__device__ float g_Q[SEQ * DOUT];          // 32 MB
__device__ float g_K[SEQ * (NKV * HD)];    // 8 MB
__device__ float g_V[SEQ * (NKV * HD)];    // 8 MB
__device__ float g_ctx[SEQ * DOUT];        // 32 MB

// ---------------------------------------------------------------------------
// tf32 tensor-core GEMM: C[M,N] = A[M,K] @ B[N,K]^T (row-major, "NT")
// 128x128 block tile, BK=32, 256 threads (8 warps), warp tile 64x32,
// mma.sync.m16n8k8 tf32, double-buffered smem.
// Smem layout: As/Bs stored row-major with stride 36 floats (pad 4) so that
// fragment loads (bank = 4*groupID + tig) are conflict-free.
// ---------------------------------------------------------------------------
#define GBK   32
#define GSTR  36            // row stride in floats
#define GBUF  (128 * GSTR)  // one buffer = 4608 floats

__device__ __forceinline__ float f2tf32(float x) {
    float r;
    asm("cvt.rna.tf32.f32 %0, %1;" : "=f"(r) : "f"(x));
    return r;
}

__device__ __forceinline__ void mma_tf32(float* c, const uint32_t* a, const uint32_t* b) {
    asm volatile(
        "mma.sync.aligned.m16n8k8.row.col.f32.tf32.tf32.f32 "
        "{%0,%1,%2,%3}, {%4,%5,%6,%7}, {%8,%9}, {%0,%1,%2,%3};"
        : "+f"(c[0]), "+f"(c[1]), "+f"(c[2]), "+f"(c[3])
        : "r"(a[0]), "r"(a[1]), "r"(a[2]), "r"(a[3]), "r"(b[0]), "r"(b[1]));
}

__global__ __launch_bounds__(256, 1) void gemm_tf32(
    const float* __restrict__ A, const float* __restrict__ B,
    float* __restrict__ C, int M, int N, int K)
{
    extern __shared__ float sm[];
    float* Asm = sm;               // 2 buffers of [128][36]
    float* Bsm = sm + 2 * GBUF;    // 2 buffers of [128][36]

    const int tid  = threadIdx.x;
    const int bm   = blockIdx.y * 128;
    const int bn   = blockIdx.x * 128;
    const int lane = tid & 31;
    const int warp = tid >> 5;
    const int wm   = (warp & 1) * 64;   // warp m offset in tile
    const int wn   = (warp >> 1) * 32;  // warp n offset in tile
    const int gID  = lane >> 2;         // 0..7
    const int tig  = lane & 3;          // 0..3

    // global-load mapping: thread handles 4 float4s per 128x32 tile
    const int lr = tid >> 3;            // 0..31 (row base, +32*i)
    const int lc = (tid & 7) * 4;       // col {0,4,...,28}

    const float* Ap = A + (size_t)bm * K;
    const float* Bp = B + (size_t)bn * K;

    float acc[16][4];
#pragma unroll
    for (int i = 0; i < 16; i++)
#pragma unroll
        for (int j = 0; j < 4; j++) acc[i][j] = 0.f;

    float4 pa[4], pb[4];

    // prologue: load K-tile 0
#pragma unroll
    for (int i = 0; i < 4; i++) {
        pa[i] = *(const float4*)(Ap + (size_t)(lr + i * 32) * K + lc);
        pb[i] = *(const float4*)(Bp + (size_t)(lr + i * 32) * K + lc);
    }
#pragma unroll
    for (int i = 0; i < 4; i++) {
        float* ad = Asm + (lr + i * 32) * GSTR + lc;
        ad[0] = f2tf32(pa[i].x); ad[1] = f2tf32(pa[i].y);
        ad[2] = f2tf32(pa[i].z); ad[3] = f2tf32(pa[i].w);
        float* bd = Bsm + (lr + i * 32) * GSTR + lc;
        bd[0] = f2tf32(pb[i].x); bd[1] = f2tf32(pb[i].y);
        bd[2] = f2tf32(pb[i].z); bd[3] = f2tf32(pb[i].w);
    }
    __syncthreads();

    const int nK = K / GBK;
    for (int kt = 0; kt < nK; kt++) {
        // prefetch next K-tile into registers
        if (kt + 1 < nK) {
            int k0 = (kt + 1) * GBK;
#pragma unroll
            for (int i = 0; i < 4; i++) {
                pa[i] = *(const float4*)(Ap + (size_t)(lr + i * 32) * K + k0 + lc);
                pb[i] = *(const float4*)(Bp + (size_t)(lr + i * 32) * K + k0 + lc);
            }
        }

        const uint32_t* Asb = (const uint32_t*)(Asm + (kt & 1) * GBUF);
        const uint32_t* Bsb = (const uint32_t*)(Bsm + (kt & 1) * GBUF);

#pragma unroll
        for (int kk = 0; kk < 4; kk++) {
            const int k = kk * 8;
            uint32_t af[16], bf[8];
#pragma unroll
            for (int mi = 0; mi < 4; mi++) {
                int m = wm + mi * 16;
                af[mi * 4 + 0] = Asb[(m + gID)     * GSTR + k + tig];
                af[mi * 4 + 1] = Asb[(m + gID + 8) * GSTR + k + tig];
                af[mi * 4 + 2] = Asb[(m + gID)     * GSTR + k + tig + 4];
                af[mi * 4 + 3] = Asb[(m + gID + 8) * GSTR + k + tig + 4];
            }
#pragma unroll
            for (int ni = 0; ni < 4; ni++) {
                int n = wn + ni * 8;
                bf[ni * 2 + 0] = Bsb[(n + gID) * GSTR + k + tig];
                bf[ni * 2 + 1] = Bsb[(n + gID) * GSTR + k + tig + 4];
            }
#pragma unroll
            for (int mi = 0; mi < 4; mi++)
#pragma unroll
                for (int ni = 0; ni < 4; ni++)
                    mma_tf32(acc[mi * 4 + ni], &af[mi * 4], &bf[ni * 2]);
        }

        // store prefetched tile into the other buffer
        if (kt + 1 < nK) {
            float* Ad = Asm + ((kt + 1) & 1) * GBUF;
            float* Bd = Bsm + ((kt + 1) & 1) * GBUF;
#pragma unroll
            for (int i = 0; i < 4; i++) {
                float* ad = Ad + (lr + i * 32) * GSTR + lc;
                ad[0] = f2tf32(pa[i].x); ad[1] = f2tf32(pa[i].y);
                ad[2] = f2tf32(pa[i].z); ad[3] = f2tf32(pa[i].w);
                float* bd = Bd + (lr + i * 32) * GSTR + lc;
                bd[0] = f2tf32(pb[i].x); bd[1] = f2tf32(pb[i].y);
                bd[2] = f2tf32(pb[i].z); bd[3] = f2tf32(pb[i].w);
            }
        }
        __syncthreads();
    }

    // epilogue
#pragma unroll
    for (int mi = 0; mi < 4; mi++) {
#pragma unroll
        for (int ni = 0; ni < 4; ni++) {
            const float* c = acc[mi * 4 + ni];
            int r0 = bm + wm + mi * 16 + gID;
            int c0 = bn + wn + ni * 8 + tig * 2;
            *(float2*)(C + (size_t)r0 * N + c0)       = make_float2(c[0], c[1]);
            *(float2*)(C + (size_t)(r0 + 8) * N + c0) = make_float2(c[2], c[3]);
        }
    }
}

// ---------------------------------------------------------------------------
// RoPE (in place) on a [SEQ, H*128] row-major tensor.
// ---------------------------------------------------------------------------
__global__ __launch_bounds__(256) void rope_kernel(
    float* __restrict__ T, const float* __restrict__ cosT,
    const float* __restrict__ sinT, int H)
{
    int idx = blockIdx.x * blockDim.x + threadIdx.x;
    int total = SEQ * H * 64;
    if (idx >= total) return;
    int d = idx & 63;
    int h = (idx >> 6) % H;
    int s = idx / (64 * H);

    float* row = T + (size_t)s * (H * HD) + h * HD;
    float x1 = row[d];
    float x2 = row[d + 64];
    float c1 = cosT[s * HD + d],      s1 = sinT[s * HD + d];
    float c2 = cosT[s * HD + d + 64], s2 = sinT[s * HD + d + 64];
    row[d]      = fmaf(x1, c1, -x2 * s1);
    row[d + 64] = fmaf(x2, c2,  x1 * s2);
}

// ---------------------------------------------------------------------------
// Flash attention (causal, GQA). One CTA = (64 q-rows) x (one head).
// ---------------------------------------------------------------------------
#define BQ  64
#define BKV 64
#define QPAD 132
#define KPAD 68
#define SPAD 65

__global__ __launch_bounds__(256) void attn_kernel(
    const float* __restrict__ Q, const float* __restrict__ K,
    const float* __restrict__ V, float* __restrict__ ctx)
{
    const int qb  = blockIdx.x;
    const int h   = blockIdx.y;
    const int hk  = h >> 2;
    const int tid = threadIdx.x;
    const int tx  = tid & 15;
    const int ty  = tid >> 4;

    extern __shared__ float sm[];
    float* Qs   = sm;
    float* Kt   = Qs + BQ * QPAD;
    float* Vs   = Kt + HD * KPAD;
    float* Ss   = Vs + BKV * QPAD;
    float* mrow = Ss + BQ * SPAD;
    float* lrow = mrow + BQ;
    float* arow = lrow + BQ;

    const float scale = 0.08838834764831845f;

#pragma unroll
    for (int i = 0; i < 8; i++) {
        int e  = tid + i * 256;
        int r  = e >> 5;
        int c4 = e & 31;
        float4 q4 = *(const float4*)(Q + (size_t)(qb * BQ + r) * DOUT + h * HD + c4 * 4);
        float* dst = Qs + r * QPAD + c4 * 4;
        dst[0] = q4.x * scale; dst[1] = q4.y * scale;
        dst[2] = q4.z * scale; dst[3] = q4.w * scale;
    }
    if (tid < BQ) { mrow[tid] = -1e30f; lrow[tid] = 0.f; }

    float accO[4][8];
#pragma unroll
    for (int i = 0; i < 4; i++)
#pragma unroll
        for (int j = 0; j < 8; j++) accO[i][j] = 0.f;

    for (int kb = 0; kb <= qb; kb++) {
        __syncthreads();

#pragma unroll
        for (int i = 0; i < 32; i++) {
            int e = tid + i * 256;
            int r = e & 63;
            int c = e >> 6;
            Kt[c * KPAD + r] = K[(size_t)(kb * BKV + r) * (NKV * HD) + hk * HD + c];
        }
#pragma unroll
        for (int i = 0; i < 8; i++) {
            int e  = tid + i * 256;
            int r  = e >> 5;
            int c4 = e & 31;
            float4 v4 = *(const float4*)(V + (size_t)(kb * BKV + r) * (NKV * HD) + hk * HD + c4 * 4);
            float* dst = Vs + r * QPAD + c4 * 4;
            dst[0] = v4.x; dst[1] = v4.y; dst[2] = v4.z; dst[3] = v4.w;
        }
        __syncthreads();

        float accS[4][4];
#pragma unroll
        for (int i = 0; i < 4; i++)
#pragma unroll
            for (int j = 0; j < 4; j++) accS[i][j] = 0.f;

        for (int d = 0; d < HD; d++) {
            float a[4], b[4];
#pragma unroll
            for (int i = 0; i < 4; i++) a[i] = Qs[(ty * 4 + i) * QPAD + d];
#pragma unroll
            for (int j = 0; j < 4; j++) b[j] = Kt[d * KPAD + tx * 4 + j];
#pragma unroll
            for (int i = 0; i < 4; i++)
#pragma unroll
                for (int j = 0; j < 4; j++)
                    accS[i][j] = fmaf(a[i], b[j], accS[i][j]);
        }

        const bool diag = (kb == qb);
#pragma unroll
        for (int i = 0; i < 4; i++) {
            int qg = qb * BQ + ty * 4 + i;
#pragma unroll
            for (int j = 0; j < 4; j++) {
                int kg = kb * BKV + tx * 4 + j;
                float v = accS[i][j];
                if (diag && kg > qg) v = -1e30f;
                Ss[(ty * 4 + i) * SPAD + tx * 4 + j] = v;
            }
        }
        __syncthreads();

        {
            int row = tid >> 2;
            int seg = tid & 3;
            float lm = -1e30f;
#pragma unroll
            for (int c = 0; c < 16; c++)
                lm = fmaxf(lm, Ss[row * SPAD + seg * 16 + c]);
            lm = fmaxf(lm, __shfl_xor_sync(0xffffffffu, lm, 1));
            lm = fmaxf(lm, __shfl_xor_sync(0xffffffffu, lm, 2));
            float mold = mrow[row];
            float mnew = fmaxf(mold, lm);
            float alpha = __expf(mold - mnew);
            float ls = 0.f;
#pragma unroll
            for (int c = 0; c < 16; c++) {
                float p = __expf(Ss[row * SPAD + seg * 16 + c] - mnew);
                Ss[row * SPAD + seg * 16 + c] = p;
                ls += p;
            }
            ls += __shfl_xor_sync(0xffffffffu, ls, 1);
            ls += __shfl_xor_sync(0xffffffffu, ls, 2);
            if (seg == 0) {
                mrow[row] = mnew;
                lrow[row] = lrow[row] * alpha + ls;
                arow[row] = alpha;
            }
        }
        __syncthreads();

        float al[4];
#pragma unroll
        for (int i = 0; i < 4; i++) al[i] = arow[ty * 4 + i];
#pragma unroll
        for (int i = 0; i < 4; i++)
#pragma unroll
            for (int j = 0; j < 8; j++) accO[i][j] *= al[i];

        for (int k = 0; k < BKV; k++) {
            float p[4];
#pragma unroll
            for (int i = 0; i < 4; i++) p[i] = Ss[(ty * 4 + i) * SPAD + k];
            float4 v0 = *(const float4*)(Vs + k * QPAD + tx * 8);
            float4 v1 = *(const float4*)(Vs + k * QPAD + tx * 8 + 4);
            float vv[8] = {v0.x, v0.y, v0.z, v0.w, v1.x, v1.y, v1.z, v1.w};
#pragma unroll
            for (int i = 0; i < 4; i++)
#pragma unroll
                for (int j = 0; j < 8; j++)
                    accO[i][j] = fmaf(p[i], vv[j], accO[i][j]);
        }
    }

    float linv[4];
#pragma unroll
    for (int i = 0; i < 4; i++) linv[i] = 1.f / lrow[ty * 4 + i];
#pragma unroll
    for (int i = 0; i < 4; i++) {
        int r = qb * BQ + ty * 4 + i;
        float* dst = ctx + (size_t)r * DOUT + h * HD + tx * 8;
#pragma unroll
        for (int j = 0; j < 8; j++) dst[j] = accO[i][j] * linv[i];
    }
}

// ---------------------------------------------------------------------------
// Launch
// ---------------------------------------------------------------------------
extern "C" void kernel_launch(void* const* d_in, const int* in_sizes, int n_in,
                              void* d_out, int out_size)
{
    const float* x    = (const float*)d_in[0];
    const float* cosT = (const float*)d_in[1];
    const float* sinT = (const float*)d_in[2];
    const float* Wq   = (const float*)d_in[3];
    const float* Wk   = (const float*)d_in[4];
    const float* Wv   = (const float*)d_in[5];
    const float* Wo   = (const float*)d_in[6];
    float* out = (float*)d_out;

    float *Qp, *Kp, *Vp, *Cp;
    cudaGetSymbolAddress((void**)&Qp, g_Q);
    cudaGetSymbolAddress((void**)&Kp, g_K);
    cudaGetSymbolAddress((void**)&Vp, g_V);
    cudaGetSymbolAddress((void**)&Cp, g_ctx);

    const int GEMM_SMEM = 4 * GBUF * (int)sizeof(float);  // 73728 B
    cudaFuncSetAttribute(gemm_tf32, cudaFuncAttributeMaxDynamicSharedMemorySize, GEMM_SMEM);

    const int ATTN_SMEM = (BQ * QPAD + HD * KPAD + BKV * QPAD + BQ * SPAD + 3 * BQ) * 4;
    cudaFuncSetAttribute(attn_kernel, cudaFuncAttributeMaxDynamicSharedMemorySize, ATTN_SMEM);

    // Projections (tensor core tf32)
    gemm_tf32<<<dim3(DOUT / 128, SEQ / 128), 256, GEMM_SMEM>>>(x, Wq, Qp, SEQ, DOUT, DIN);
    gemm_tf32<<<dim3((NKV * HD) / 128, SEQ / 128), 256, GEMM_SMEM>>>(x, Wk, Kp, SEQ, NKV * HD, DIN);
    gemm_tf32<<<dim3((NKV * HD) / 128, SEQ / 128), 256, GEMM_SMEM>>>(x, Wv, Vp, SEQ, NKV * HD, DIN);

    // RoPE on Q and K
    {
        int totQ = SEQ * NH * 64;
        rope_kernel<<<(totQ + 255) / 256, 256>>>(Qp, cosT, sinT, NH);
        int totK = SEQ * NKV * 64;
        rope_kernel<<<(totK + 255) / 256, 256>>>(Kp, cosT, sinT, NKV);
    }

    // Flash attention
    attn_kernel<<<dim3(SEQ / BQ, NH), 256, ATTN_SMEM>>>(Qp, Kp, Vp, Cp);

    // Output projection
    gemm_tf32<<<dim3(DOUT / 128, SEQ / 128), 256, GEMM_SMEM>>>(Cp, Wo, out, SEQ, DOUT, DIN);
}

// round 3
// speedup vs baseline: 3.3593x; 1.5699x over previous
#include <cuda_runtime.h>
#include <cuda_bf16.h>
#include <math.h>
#include <stdint.h>

// Problem constants
#define SEQ    2048
#define DIN    4096
#define DOUT   4096
#define NH     32
#define NKV    8
#define HD     128
#define GROUP  4

// Scratch buffers (allocation-free rule: use __device__ globals)
__device__ float g_Q[SEQ * DOUT];          // 32 MB
__device__ float g_K[SEQ * (NKV * HD)];    // 8 MB
__device__ float g_V[SEQ * (NKV * HD)];    // 8 MB
__device__ float g_ctx[SEQ * DOUT];        // 32 MB

__device__ __forceinline__ float f2tf32(float x) {
    float r;
    asm("cvt.rna.tf32.f32 %0, %1;" : "=f"(r) : "f"(x));
    return r;
}

__device__ __forceinline__ void mma_tf32(float* c, const uint32_t* a, const uint32_t* b) {
    asm volatile(
        "mma.sync.aligned.m16n8k8.row.col.f32.tf32.tf32.f32 "
        "{%0,%1,%2,%3}, {%4,%5,%6,%7}, {%8,%9}, {%0,%1,%2,%3};"
        : "+f"(c[0]), "+f"(c[1]), "+f"(c[2]), "+f"(c[3])
        : "r"(a[0]), "r"(a[1]), "r"(a[2]), "r"(a[3]), "r"(b[0]), "r"(b[1]));
}

// ---------------------------------------------------------------------------
// tf32 tensor-core GEMM: C[M,N] = A[M,K] @ B[N,K]^T (row-major, "NT")
// (unchanged from Round 2 — validated)
// ---------------------------------------------------------------------------
#define GBK   32
#define GSTR  36
#define GBUF  (128 * GSTR)

__global__ __launch_bounds__(256, 1) void gemm_tf32(
    const float* __restrict__ A, const float* __restrict__ B,
    float* __restrict__ C, int M, int N, int K)
{
    extern __shared__ float sm[];
    float* Asm = sm;
    float* Bsm = sm + 2 * GBUF;

    const int tid  = threadIdx.x;
    const int bm   = blockIdx.y * 128;
    const int bn   = blockIdx.x * 128;
    const int lane = tid & 31;
    const int warp = tid >> 5;
    const int wm   = (warp & 1) * 64;
    const int wn   = (warp >> 1) * 32;
    const int gID  = lane >> 2;
    const int tig  = lane & 3;

    const int lr = tid >> 3;
    const int lc = (tid & 7) * 4;

    const float* Ap = A + (size_t)bm * K;
    const float* Bp = B + (size_t)bn * K;

    float acc[16][4];
#pragma unroll
    for (int i = 0; i < 16; i++)
#pragma unroll
        for (int j = 0; j < 4; j++) acc[i][j] = 0.f;

    float4 pa[4], pb[4];

#pragma unroll
    for (int i = 0; i < 4; i++) {
        pa[i] = *(const float4*)(Ap + (size_t)(lr + i * 32) * K + lc);
        pb[i] = *(const float4*)(Bp + (size_t)(lr + i * 32) * K + lc);
    }
#pragma unroll
    for (int i = 0; i < 4; i++) {
        float* ad = Asm + (lr + i * 32) * GSTR + lc;
        ad[0] = f2tf32(pa[i].x); ad[1] = f2tf32(pa[i].y);
        ad[2] = f2tf32(pa[i].z); ad[3] = f2tf32(pa[i].w);
        float* bd = Bsm + (lr + i * 32) * GSTR + lc;
        bd[0] = f2tf32(pb[i].x); bd[1] = f2tf32(pb[i].y);
        bd[2] = f2tf32(pb[i].z); bd[3] = f2tf32(pb[i].w);
    }
    __syncthreads();

    const int nK = K / GBK;
    for (int kt = 0; kt < nK; kt++) {
        if (kt + 1 < nK) {
            int k0 = (kt + 1) * GBK;
#pragma unroll
            for (int i = 0; i < 4; i++) {
                pa[i] = *(const float4*)(Ap + (size_t)(lr + i * 32) * K + k0 + lc);
                pb[i] = *(const float4*)(Bp + (size_t)(lr + i * 32) * K + k0 + lc);
            }
        }

        const uint32_t* Asb = (const uint32_t*)(Asm + (kt & 1) * GBUF);
        const uint32_t* Bsb = (const uint32_t*)(Bsm + (kt & 1) * GBUF);

#pragma unroll
        for (int kk = 0; kk < 4; kk++) {
            const int k = kk * 8;
            uint32_t af[16], bf[8];
#pragma unroll
            for (int mi = 0; mi < 4; mi++) {
                int m = wm + mi * 16;
                af[mi * 4 + 0] = Asb[(m + gID)     * GSTR + k + tig];
                af[mi * 4 + 1] = Asb[(m + gID + 8) * GSTR + k + tig];
                af[mi * 4 + 2] = Asb[(m + gID)     * GSTR + k + tig + 4];
                af[mi * 4 + 3] = Asb[(m + gID + 8) * GSTR + k + tig + 4];
            }
#pragma unroll
            for (int ni = 0; ni < 4; ni++) {
                int n = wn + ni * 8;
                bf[ni * 2 + 0] = Bsb[(n + gID) * GSTR + k + tig];
                bf[ni * 2 + 1] = Bsb[(n + gID) * GSTR + k + tig + 4];
            }
#pragma unroll
            for (int mi = 0; mi < 4; mi++)
#pragma unroll
                for (int ni = 0; ni < 4; ni++)
                    mma_tf32(acc[mi * 4 + ni], &af[mi * 4], &bf[ni * 2]);
        }

        if (kt + 1 < nK) {
            float* Ad = Asm + ((kt + 1) & 1) * GBUF;
            float* Bd = Bsm + ((kt + 1) & 1) * GBUF;
#pragma unroll
            for (int i = 0; i < 4; i++) {
                float* ad = Ad + (lr + i * 32) * GSTR + lc;
                ad[0] = f2tf32(pa[i].x); ad[1] = f2tf32(pa[i].y);
                ad[2] = f2tf32(pa[i].z); ad[3] = f2tf32(pa[i].w);
                float* bd = Bd + (lr + i * 32) * GSTR + lc;
                bd[0] = f2tf32(pb[i].x); bd[1] = f2tf32(pb[i].y);
                bd[2] = f2tf32(pb[i].z); bd[3] = f2tf32(pb[i].w);
            }
        }
        __syncthreads();
    }

#pragma unroll
    for (int mi = 0; mi < 4; mi++) {
#pragma unroll
        for (int ni = 0; ni < 4; ni++) {
            const float* c = acc[mi * 4 + ni];
            int r0 = bm + wm + mi * 16 + gID;
            int c0 = bn + wn + ni * 8 + tig * 2;
            *(float2*)(C + (size_t)r0 * N + c0)       = make_float2(c[0], c[1]);
            *(float2*)(C + (size_t)(r0 + 8) * N + c0) = make_float2(c[2], c[3]);
        }
    }
}

// ---------------------------------------------------------------------------
// RoPE (in place) on a [SEQ, H*128] row-major tensor.
// ---------------------------------------------------------------------------
__global__ __launch_bounds__(256) void rope_kernel(
    float* __restrict__ T, const float* __restrict__ cosT,
    const float* __restrict__ sinT, int H)
{
    int idx = blockIdx.x * blockDim.x + threadIdx.x;
    int total = SEQ * H * 64;
    if (idx >= total) return;
    int d = idx & 63;
    int h = (idx >> 6) % H;
    int s = idx / (64 * H);

    float* row = T + (size_t)s * (H * HD) + h * HD;
    float x1 = row[d];
    float x2 = row[d + 64];
    float c1 = cosT[s * HD + d],      s1 = sinT[s * HD + d];
    float c2 = cosT[s * HD + d + 64], s2 = sinT[s * HD + d + 64];
    row[d]      = fmaf(x1, c1, -x2 * s1);
    row[d + 64] = fmaf(x2, c2,  x1 * s2);
}

// ---------------------------------------------------------------------------
// Tensor-core flash attention (causal, GQA), tf32 mma.m16n8k8.
// CTA = 128 threads (4 warps), BQ=64 rows x one head. Warp owns 16 q-rows.
// Smem strides chosen so all fragment LDS are bank-conflict-free:
//   Qs/Ks stride 132 (A/B frag bank = 4*gID+tig), Vs stride 136 (8*tig+gID),
//   Ps stride 68.
// ---------------------------------------------------------------------------
#define BQ   64
#define BKV  64
#define QKS  132
#define VS_  136
#define PS_  68

__global__ __launch_bounds__(128, 1) void attn_mma(
    const float* __restrict__ Q, const float* __restrict__ K,
    const float* __restrict__ V, float* __restrict__ ctx)
{
    const int qb  = gridDim.x - 1 - blockIdx.x;   // long rows first
    const int h   = blockIdx.y;
    const int hk  = h >> 2;
    const int tid = threadIdx.x;
    const int lane = tid & 31;
    const int warp = tid >> 5;
    const int gID  = lane >> 2;
    const int tig  = lane & 3;
    const int wrow = warp * 16;     // warp's q-row offset in tile

    extern __shared__ float sm[];
    float* Qs = sm;                  // [64][132]
    float* Ks = Qs + BQ * QKS;       // [64][132]
    float* Vs = Ks + BKV * QKS;      // [64][136]
    float* Ps = Vs + BKV * VS_;      // [64][68]

    const float scale = 0.08838834764831845f;  // 1/sqrt(128)

    // Load Q tile (scaled + tf32). 64 rows x 128 cols, 128 threads.
    {
        int r = tid >> 1;                  // 0..63
        int cb = (tid & 1) * 64;           // 0 or 64
        const float* src = Q + (size_t)(qb * BQ + r) * DOUT + h * HD + cb;
        float* dst = Qs + r * QKS + cb;
#pragma unroll
        for (int c = 0; c < 64; c += 4) {
            float4 q4 = *(const float4*)(src + c);
            dst[c + 0] = f2tf32(q4.x * scale);
            dst[c + 1] = f2tf32(q4.y * scale);
            dst[c + 2] = f2tf32(q4.z * scale);
            dst[c + 3] = f2tf32(q4.w * scale);
        }
    }

    // online softmax state: rows (wrow+gID), (wrow+gID+8); replicated in quad
    float mrow[2] = {-1e30f, -1e30f};
    float lrow[2] = {0.f, 0.f};
    float accO[16][4];
#pragma unroll
    for (int i = 0; i < 16; i++)
#pragma unroll
        for (int j = 0; j < 4; j++) accO[i][j] = 0.f;

    for (int kb = 0; kb <= qb; kb++) {
        __syncthreads();   // prev iter done reading Ks/Vs

        // Load K,V tiles (tf32). 64x128 each, 128 threads -> 64 floats each.
        {
            int r = tid >> 1;
            int cb = (tid & 1) * 64;
            const float* ksrc = K + (size_t)(kb * BKV + r) * (NKV * HD) + hk * HD + cb;
            const float* vsrc = V + (size_t)(kb * BKV + r) * (NKV * HD) + hk * HD + cb;
            float* kdst = Ks + r * QKS + cb;
            float* vdst = Vs + r * VS_ + cb;
#pragma unroll
            for (int c = 0; c < 64; c += 4) {
                float4 k4 = *(const float4*)(ksrc + c);
                kdst[c + 0] = f2tf32(k4.x); kdst[c + 1] = f2tf32(k4.y);
                kdst[c + 2] = f2tf32(k4.z); kdst[c + 3] = f2tf32(k4.w);
                float4 v4 = *(const float4*)(vsrc + c);
                vdst[c + 0] = f2tf32(v4.x); vdst[c + 1] = f2tf32(v4.y);
                vdst[c + 2] = f2tf32(v4.z); vdst[c + 3] = f2tf32(v4.w);
            }
        }
        __syncthreads();

        // ---- S = Q @ K^T : warp computes 16x64 ----
        float accS[8][4];
#pragma unroll
        for (int i = 0; i < 8; i++)
#pragma unroll
            for (int j = 0; j < 4; j++) accS[i][j] = 0.f;

        const uint32_t* Qu = (const uint32_t*)Qs;
        const uint32_t* Ku = (const uint32_t*)Ks;
#pragma unroll
        for (int ks = 0; ks < 16; ks++) {
            const int k = ks * 8;
            uint32_t a[4];
            a[0] = Qu[(wrow + gID)     * QKS + k + tig];
            a[1] = Qu[(wrow + gID + 8) * QKS + k + tig];
            a[2] = Qu[(wrow + gID)     * QKS + k + tig + 4];
            a[3] = Qu[(wrow + gID + 8) * QKS + k + tig + 4];
#pragma unroll
            for (int nt = 0; nt < 8; nt++) {
                uint32_t b[2];
                b[0] = Ku[(nt * 8 + gID) * QKS + k + tig];
                b[1] = Ku[(nt * 8 + gID) * QKS + k + tig + 4];
                mma_tf32(accS[nt], a, b);
            }
        }

        // ---- causal mask on diagonal tile ----
        if (kb == qb) {
            int r0 = wrow + gID;          // local row (tile-relative)
            int r1 = r0 + 8;
#pragma unroll
            for (int nt = 0; nt < 8; nt++) {
                int c0 = nt * 8 + 2 * tig;
                if (c0 > r0)     accS[nt][0] = -1e30f;
                if (c0 + 1 > r0) accS[nt][1] = -1e30f;
                if (c0 > r1)     accS[nt][2] = -1e30f;
                if (c0 + 1 > r1) accS[nt][3] = -1e30f;
            }
        }

        // ---- online softmax (register) ----
        float mx0 = -1e30f, mx1 = -1e30f;
#pragma unroll
        for (int nt = 0; nt < 8; nt++) {
            mx0 = fmaxf(mx0, fmaxf(accS[nt][0], accS[nt][1]));
            mx1 = fmaxf(mx1, fmaxf(accS[nt][2], accS[nt][3]));
        }
        mx0 = fmaxf(mx0, __shfl_xor_sync(0xffffffffu, mx0, 1));
        mx0 = fmaxf(mx0, __shfl_xor_sync(0xffffffffu, mx0, 2));
        mx1 = fmaxf(mx1, __shfl_xor_sync(0xffffffffu, mx1, 1));
        mx1 = fmaxf(mx1, __shfl_xor_sync(0xffffffffu, mx1, 2));

        float mn0 = fmaxf(mrow[0], mx0);
        float mn1 = fmaxf(mrow[1], mx1);
        float al0 = __expf(mrow[0] - mn0);
        float al1 = __expf(mrow[1] - mn1);
        mrow[0] = mn0; mrow[1] = mn1;

        float ls0 = 0.f, ls1 = 0.f;
        float* Pw = Ps;
#pragma unroll
        for (int nt = 0; nt < 8; nt++) {
            float p0 = __expf(accS[nt][0] - mn0);
            float p1 = __expf(accS[nt][1] - mn0);
            float p2 = __expf(accS[nt][2] - mn1);
            float p3 = __expf(accS[nt][3] - mn1);
            ls0 += p0 + p1;
            ls1 += p2 + p3;
            int c = nt * 8 + 2 * tig;
            *(float2*)(Pw + (wrow + gID)     * PS_ + c) = make_float2(f2tf32(p0), f2tf32(p1));
            *(float2*)(Pw + (wrow + gID + 8) * PS_ + c) = make_float2(f2tf32(p2), f2tf32(p3));
        }
        ls0 += __shfl_xor_sync(0xffffffffu, ls0, 1);
        ls0 += __shfl_xor_sync(0xffffffffu, ls0, 2);
        ls1 += __shfl_xor_sync(0xffffffffu, ls1, 1);
        ls1 += __shfl_xor_sync(0xffffffffu, ls1, 2);
        lrow[0] = lrow[0] * al0 + ls0;
        lrow[1] = lrow[1] * al1 + ls1;

        // rescale O accumulator
#pragma unroll
        for (int nt = 0; nt < 16; nt++) {
            accO[nt][0] *= al0; accO[nt][1] *= al0;
            accO[nt][2] *= al1; accO[nt][3] *= al1;
        }
        __syncwarp();   // Ps rows are warp-private; warp sync suffices

        // ---- O += P @ V : warp computes 16x128 ----
        const uint32_t* Pu = (const uint32_t*)Ps;
        const uint32_t* Vu = (const uint32_t*)Vs;
#pragma unroll
        for (int ks = 0; ks < 8; ks++) {
            const int k = ks * 8;
            uint32_t a[4];
            a[0] = Pu[(wrow + gID)     * PS_ + k + tig];
            a[1] = Pu[(wrow + gID + 8) * PS_ + k + tig];
            a[2] = Pu[(wrow + gID)     * PS_ + k + tig + 4];
            a[3] = Pu[(wrow + gID + 8) * PS_ + k + tig + 4];
#pragma unroll
            for (int nt = 0; nt < 16; nt++) {
                uint32_t b[2];
                b[0] = Vu[(k + tig)     * VS_ + nt * 8 + gID];
                b[1] = Vu[(k + tig + 4) * VS_ + nt * 8 + gID];
                mma_tf32(accO[nt], a, b);
            }
        }
    }

    // epilogue: normalize and store
    float li0 = 1.f / lrow[0];
    float li1 = 1.f / lrow[1];
    int r0 = qb * BQ + wrow + gID;
    int r1 = r0 + 8;
#pragma unroll
    for (int nt = 0; nt < 16; nt++) {
        int c = h * HD + nt * 8 + 2 * tig;
        *(float2*)(ctx + (size_t)r0 * DOUT + c) =
            make_float2(accO[nt][0] * li0, accO[nt][1] * li0);
        *(float2*)(ctx + (size_t)r1 * DOUT + c) =
            make_float2(accO[nt][2] * li1, accO[nt][3] * li1);
    }
}

// ---------------------------------------------------------------------------
// Launch
// ---------------------------------------------------------------------------
extern "C" void kernel_launch(void* const* d_in, const int* in_sizes, int n_in,
                              void* d_out, int out_size)
{
    const float* x    = (const float*)d_in[0];
    const float* cosT = (const float*)d_in[1];
    const float* sinT = (const float*)d_in[2];
    const float* Wq   = (const float*)d_in[3];
    const float* Wk   = (const float*)d_in[4];
    const float* Wv   = (const float*)d_in[5];
    const float* Wo   = (const float*)d_in[6];
    float* out = (float*)d_out;

    float *Qp, *Kp, *Vp, *Cp;
    cudaGetSymbolAddress((void**)&Qp, g_Q);
    cudaGetSymbolAddress((void**)&Kp, g_K);
    cudaGetSymbolAddress((void**)&Vp, g_V);
    cudaGetSymbolAddress((void**)&Cp, g_ctx);

    const int GEMM_SMEM = 4 * GBUF * (int)sizeof(float);
    cudaFuncSetAttribute(gemm_tf32, cudaFuncAttributeMaxDynamicSharedMemorySize, GEMM_SMEM);

    const int ATTN_SMEM = (BQ * QKS + BKV * QKS + BKV * VS_ + BQ * PS_) * (int)sizeof(float);
    cudaFuncSetAttribute(attn_mma, cudaFuncAttributeMaxDynamicSharedMemorySize, ATTN_SMEM);

    // Projections (tensor core tf32)
    gemm_tf32<<<dim3(DOUT / 128, SEQ / 128), 256, GEMM_SMEM>>>(x, Wq, Qp, SEQ, DOUT, DIN);
    gemm_tf32<<<dim3((NKV * HD) / 128, SEQ / 128), 256, GEMM_SMEM>>>(x, Wk, Kp, SEQ, NKV * HD, DIN);
    gemm_tf32<<<dim3((NKV * HD) / 128, SEQ / 128), 256, GEMM_SMEM>>>(x, Wv, Vp, SEQ, NKV * HD, DIN);

    // RoPE on Q and K
    {
        int totQ = SEQ * NH * 64;
        rope_kernel<<<(totQ + 255) / 256, 256>>>(Qp, cosT, sinT, NH);
        int totK = SEQ * NKV * 64;
        rope_kernel<<<(totK + 255) / 256, 256>>>(Kp, cosT, sinT, NKV);
    }

    // Tensor-core flash attention
    attn_mma<<<dim3(SEQ / BQ, NH), 128, ATTN_SMEM>>>(Qp, Kp, Vp, Cp);

    // Output projection
    gemm_tf32<<<dim3(DOUT / 128, SEQ / 128), 256, GEMM_SMEM>>>(Cp, Wo, out, SEQ, DOUT, DIN);
}

// round 5
// speedup vs baseline: 4.1811x; 1.2446x over previous
#include <cuda_runtime.h>
#include <cuda_bf16.h>
#include <math.h>
#include <stdint.h>

// Problem constants
#define SEQ    2048
#define DIN    4096
#define DOUT   4096
#define NH     32
#define NKV    8
#define HD     128
#define GROUP  4

// Scratch buffers
__device__ float g_Q[SEQ * DOUT];
__device__ float g_K[SEQ * (NKV * HD)];
__device__ float g_V[SEQ * (NKV * HD)];
__device__ float g_ctx[SEQ * DOUT];

__device__ __forceinline__ float f2tf32(float x) {
    float r;
    asm("cvt.rna.tf32.f32 %0, %1;" : "=f"(r) : "f"(x));
    return r;
}

__device__ __forceinline__ uint32_t cvt_u(uint32_t u) {
    float f = __uint_as_float(u);
    asm("cvt.rna.tf32.f32 %0, %1;" : "=f"(f) : "f"(f));
    return __float_as_uint(f);
}

__device__ __forceinline__ void mma_tf32(float* c, const uint32_t* a, const uint32_t* b) {
    asm volatile(
        "mma.sync.aligned.m16n8k8.row.col.f32.tf32.tf32.f32 "
        "{%0,%1,%2,%3}, {%4,%5,%6,%7}, {%8,%9}, {%0,%1,%2,%3};"
        : "+f"(c[0]), "+f"(c[1]), "+f"(c[2]), "+f"(c[3])
        : "r"(a[0]), "r"(a[1]), "r"(a[2]), "r"(a[3]), "r"(b[0]), "r"(b[1]));
}

__device__ __forceinline__ uint32_t smem_u32(const void* p) {
    uint32_t a;
    asm("{ .reg .u64 t; cvta.to.shared.u64 t, %1; cvt.u32.u64 %0, t; }"
        : "=r"(a) : "l"(p));
    return a;
}

__device__ __forceinline__ void cp16(uint32_t dst, const float* src) {
    asm volatile("cp.async.cg.shared.global [%0], [%1], 16;"
                 :: "r"(dst), "l"(src) : "memory");
}
#define CP_COMMIT() asm volatile("cp.async.commit_group;" ::: "memory")
#define CP_WAIT(n)  asm volatile("cp.async.wait_group %0;" :: "n"(n) : "memory")

// ===========================================================================
// cp.async tf32 GEMM core: C[128,128] tile of A[M,K] @ B[N,K]^T.
// 128 threads, 4 warps, warp tile 64x64, BK=32, 3-stage cp.async ring.
// Smem tile layout: row r (128B = 32 floats), 16B chunk c stored at
//   r*128 + (c ^ (r&7))*16   (SW128 xor swizzle -> conflict-free frags)
// A caller passes A (+bm rows inside), B pre-offset to its n-row block,
// C pre-offset to the output column block.
// ===========================================================================
#define GS 3
#define STAGE_BYTES 32768
#define GEMM_SMEM (GS * STAGE_BYTES)

__device__ __forceinline__ void gemm_core(
    const float* __restrict__ A, const float* __restrict__ B,
    float* __restrict__ C, int K, int ldc, int bm)
{
    extern __shared__ char sbuf[];
    const uint32_t sbase = smem_u32(sbuf);
    const int tid  = threadIdx.x;
    const int lane = tid & 31;
    const int warp = tid >> 5;
    const int gID  = lane >> 2;
    const int tig  = lane & 3;
    const int wm   = (warp & 1) * 64;
    const int wn   = (warp >> 1) * 64;

    // fill mapping: thread -> rows (tid>>3)+16*i, 16B chunk (tid&7)
    const int fr = tid >> 3;
    const int fc = tid & 7;

    float acc[4][8][4];
#pragma unroll
    for (int mi = 0; mi < 4; mi++)
#pragma unroll
        for (int ni = 0; ni < 8; ni++)
#pragma unroll
            for (int j = 0; j < 4; j++) acc[mi][ni][j] = 0.f;

    const int nK = K >> 5;

    // ---- stage fill (cp.async) ----
    auto fill = [&](int st, int kt) {
        const uint32_t dA = sbase + st * STAGE_BYTES;
        const uint32_t dB = dA + 16384;
        const float* gA = A + (size_t)bm * K + kt * 32;
        const float* gB = B + (size_t)kt * 32;
#pragma unroll
        for (int i = 0; i < 8; i++) {
            const int r = fr + i * 16;
            const uint32_t sw = (uint32_t)(r * 128 + ((fc ^ (r & 7)) * 16));
            cp16(dA + sw, gA + (size_t)r * K + fc * 4);
            cp16(dB + sw, gB + (size_t)r * K + fc * 4);
        }
    };

    // prologue: stages 0..GS-2
#pragma unroll
    for (int s = 0; s < GS - 1; s++) {
        if (s < nK) fill(s, s);
        CP_COMMIT();
    }

    for (int kt = 0; kt < nK; kt++) {
        const int nxt = kt + GS - 1;
        if (nxt < nK) fill(nxt % GS, nxt);
        CP_COMMIT();
        CP_WAIT(2);          // stage kt's group is complete
        __syncthreads();

        const uint32_t* Sa = (const uint32_t*)(sbuf + (kt % GS) * STAGE_BYTES);
        const uint32_t* Sb = Sa + 4096;

#pragma unroll
        for (int kk = 0; kk < 4; kk++) {
            const int K4 = kk * 2;
            const int x0 = ((K4 ^ gID) * 4 + tig);
            const int x1 = (((K4 + 1) ^ gID) * 4 + tig);

            uint32_t af[4][4], bf[8][2];
#pragma unroll
            for (int mi = 0; mi < 4; mi++) {
                const int r = wm + mi * 16 + gID;
                af[mi][0] = cvt_u(Sa[r * 32 + x0]);
                af[mi][1] = cvt_u(Sa[(r + 8) * 32 + x0]);
                af[mi][2] = cvt_u(Sa[r * 32 + x1]);
                af[mi][3] = cvt_u(Sa[(r + 8) * 32 + x1]);
            }
#pragma unroll
            for (int ni = 0; ni < 8; ni++) {
                const int n = wn + ni * 8 + gID;
                bf[ni][0] = cvt_u(Sb[n * 32 + x0]);
                bf[ni][1] = cvt_u(Sb[n * 32 + x1]);
            }
#pragma unroll
            for (int mi = 0; mi < 4; mi++)
#pragma unroll
                for (int ni = 0; ni < 8; ni++)
                    mma_tf32(acc[mi][ni], af[mi], bf[ni]);
        }
        __syncthreads();
    }

    // epilogue
#pragma unroll
    for (int mi = 0; mi < 4; mi++) {
        const int r0 = bm + wm + mi * 16 + gID;
#pragma unroll
        for (int ni = 0; ni < 8; ni++) {
            const int c0 = wn + ni * 8 + tig * 2;
            const float* c = acc[mi][ni];
            *(float2*)(C + (size_t)r0 * ldc + c0)       = make_float2(c[0], c[1]);
            *(float2*)(C + (size_t)(r0 + 8) * ldc + c0) = make_float2(c[2], c[3]);
        }
    }
}

// Fused QKV projection: n-blocks 0..31 -> Q, 32..39 -> K, 40..47 -> V
__global__ __launch_bounds__(128, 2) void gemm_qkv(
    const float* __restrict__ x,
    const float* __restrict__ Wq, const float* __restrict__ Wk,
    const float* __restrict__ Wv,
    float* __restrict__ Q, float* __restrict__ Ko, float* __restrict__ Vo)
{
    const int bn = blockIdx.x;
    const int bm = blockIdx.y * 128;
    const float* B;
    float* C;
    int ldc, coff;
    if (bn < 32)      { B = Wq; C = Q;  ldc = DOUT; coff = bn * 128; }
    else if (bn < 40) { B = Wk; C = Ko; ldc = NKV * HD; coff = (bn - 32) * 128; }
    else              { B = Wv; C = Vo; ldc = NKV * HD; coff = (bn - 40) * 128; }
    gemm_core(x, B + (size_t)coff * DIN, C + coff, DIN, ldc, bm);
}

// Generic NT GEMM (used for O projection)
__global__ __launch_bounds__(128, 2) void gemm_nt(
    const float* __restrict__ A, const float* __restrict__ B,
    float* __restrict__ C, int K, int N)
{
    const int coff = blockIdx.x * 128;
    gemm_core(A, B + (size_t)coff * K, C + coff, K, N, blockIdx.y * 128);
}

// ---------------------------------------------------------------------------
// RoPE (in place) on a [SEQ, H*128] row-major tensor.
// ---------------------------------------------------------------------------
__global__ __launch_bounds__(256) void rope_kernel(
    float* __restrict__ T, const float* __restrict__ cosT,
    const float* __restrict__ sinT, int H)
{
    int idx = blockIdx.x * blockDim.x + threadIdx.x;
    int total = SEQ * H * 64;
    if (idx >= total) return;
    int d = idx & 63;
    int h = (idx >> 6) % H;
    int s = idx / (64 * H);

    float* row = T + (size_t)s * (H * HD) + h * HD;
    float x1 = row[d];
    float x2 = row[d + 64];
    float c1 = cosT[s * HD + d],      s1 = sinT[s * HD + d];
    float c2 = cosT[s * HD + d + 64], s2 = sinT[s * HD + d + 64];
    row[d]      = fmaf(x1, c1, -x2 * s1);
    row[d + 64] = fmaf(x2, c2,  x1 * s2);
}

// ---------------------------------------------------------------------------
// Tensor-core flash attention (causal, GQA), tf32 mma.m16n8k8.
// (unchanged from Round 3 — validated)
// ---------------------------------------------------------------------------
#define BQ   64
#define BKV  64
#define QKS  132
#define VS_  136
#define PS_  68

__global__ __launch_bounds__(128, 1) void attn_mma(
    const float* __restrict__ Q, const float* __restrict__ K,
    const float* __restrict__ V, float* __restrict__ ctx)
{
    const int qb  = gridDim.x - 1 - blockIdx.x;
    const int h   = blockIdx.y;
    const int hk  = h >> 2;
    const int tid = threadIdx.x;
    const int lane = tid & 31;
    const int warp = tid >> 5;
    const int gID  = lane >> 2;
    const int tig  = lane & 3;
    const int wrow = warp * 16;

    extern __shared__ float sm[];
    float* Qs = sm;
    float* Ks = Qs + BQ * QKS;
    float* Vs = Ks + BKV * QKS;
    float* Ps = Vs + BKV * VS_;

    const float scale = 0.08838834764831845f;

    {
        int r = tid >> 1;
        int cb = (tid & 1) * 64;
        const float* src = Q + (size_t)(qb * BQ + r) * DOUT + h * HD + cb;
        float* dst = Qs + r * QKS + cb;
#pragma unroll
        for (int c = 0; c < 64; c += 4) {
            float4 q4 = *(const float4*)(src + c);
            dst[c + 0] = f2tf32(q4.x * scale);
            dst[c + 1] = f2tf32(q4.y * scale);
            dst[c + 2] = f2tf32(q4.z * scale);
            dst[c + 3] = f2tf32(q4.w * scale);
        }
    }

    float mrow[2] = {-1e30f, -1e30f};
    float lrow[2] = {0.f, 0.f};
    float accO[16][4];
#pragma unroll
    for (int i = 0; i < 16; i++)
#pragma unroll
        for (int j = 0; j < 4; j++) accO[i][j] = 0.f;

    for (int kb = 0; kb <= qb; kb++) {
        __syncthreads();

        {
            int r = tid >> 1;
            int cb = (tid & 1) * 64;
            const float* ksrc = K + (size_t)(kb * BKV + r) * (NKV * HD) + hk * HD + cb;
            const float* vsrc = V + (size_t)(kb * BKV + r) * (NKV * HD) + hk * HD + cb;
            float* kdst = Ks + r * QKS + cb;
            float* vdst = Vs + r * VS_ + cb;
#pragma unroll
            for (int c = 0; c < 64; c += 4) {
                float4 k4 = *(const float4*)(ksrc + c);
                kdst[c + 0] = f2tf32(k4.x); kdst[c + 1] = f2tf32(k4.y);
                kdst[c + 2] = f2tf32(k4.z); kdst[c + 3] = f2tf32(k4.w);
                float4 v4 = *(const float4*)(vsrc + c);
                vdst[c + 0] = f2tf32(v4.x); vdst[c + 1] = f2tf32(v4.y);
                vdst[c + 2] = f2tf32(v4.z); vdst[c + 3] = f2tf32(v4.w);
            }
        }
        __syncthreads();

        float accS[8][4];
#pragma unroll
        for (int i = 0; i < 8; i++)
#pragma unroll
            for (int j = 0; j < 4; j++) accS[i][j] = 0.f;

        const uint32_t* Qu = (const uint32_t*)Qs;
        const uint32_t* Ku = (const uint32_t*)Ks;
#pragma unroll
        for (int ks = 0; ks < 16; ks++) {
            const int k = ks * 8;
            uint32_t a[4];
            a[0] = Qu[(wrow + gID)     * QKS + k + tig];
            a[1] = Qu[(wrow + gID + 8) * QKS + k + tig];
            a[2] = Qu[(wrow + gID)     * QKS + k + tig + 4];
            a[3] = Qu[(wrow + gID + 8) * QKS + k + tig + 4];
#pragma unroll
            for (int nt = 0; nt < 8; nt++) {
                uint32_t b[2];
                b[0] = Ku[(nt * 8 + gID) * QKS + k + tig];
                b[1] = Ku[(nt * 8 + gID) * QKS + k + tig + 4];
                mma_tf32(accS[nt], a, b);
            }
        }

        if (kb == qb) {
            int r0 = wrow + gID;
            int r1 = r0 + 8;
#pragma unroll
            for (int nt = 0; nt < 8; nt++) {
                int c0 = nt * 8 + 2 * tig;
                if (c0 > r0)     accS[nt][0] = -1e30f;
                if (c0 + 1 > r0) accS[nt][1] = -1e30f;
                if (c0 > r1)     accS[nt][2] = -1e30f;
                if (c0 + 1 > r1) accS[nt][3] = -1e30f;
            }
        }

        float mx0 = -1e30f, mx1 = -1e30f;
#pragma unroll
        for (int nt = 0; nt < 8; nt++) {
            mx0 = fmaxf(mx0, fmaxf(accS[nt][0], accS[nt][1]));
            mx1 = fmaxf(mx1, fmaxf(accS[nt][2], accS[nt][3]));
        }
        mx0 = fmaxf(mx0, __shfl_xor_sync(0xffffffffu, mx0, 1));
        mx0 = fmaxf(mx0, __shfl_xor_sync(0xffffffffu, mx0, 2));
        mx1 = fmaxf(mx1, __shfl_xor_sync(0xffffffffu, mx1, 1));
        mx1 = fmaxf(mx1, __shfl_xor_sync(0xffffffffu, mx1, 2));

        float mn0 = fmaxf(mrow[0], mx0);
        float mn1 = fmaxf(mrow[1], mx1);
        float al0 = __expf(mrow[0] - mn0);
        float al1 = __expf(mrow[1] - mn1);
        mrow[0] = mn0; mrow[1] = mn1;

        float ls0 = 0.f, ls1 = 0.f;
#pragma unroll
        for (int nt = 0; nt < 8; nt++) {
            float p0 = __expf(accS[nt][0] - mn0);
            float p1 = __expf(accS[nt][1] - mn0);
            float p2 = __expf(accS[nt][2] - mn1);
            float p3 = __expf(accS[nt][3] - mn1);
            ls0 += p0 + p1;
            ls1 += p2 + p3;
            int c = nt * 8 + 2 * tig;
            *(float2*)(Ps + (wrow + gID)     * PS_ + c) = make_float2(f2tf32(p0), f2tf32(p1));
            *(float2*)(Ps + (wrow + gID + 8) * PS_ + c) = make_float2(f2tf32(p2), f2tf32(p3));
        }
        ls0 += __shfl_xor_sync(0xffffffffu, ls0, 1);
        ls0 += __shfl_xor_sync(0xffffffffu, ls0, 2);
        ls1 += __shfl_xor_sync(0xffffffffu, ls1, 1);
        ls1 += __shfl_xor_sync(0xffffffffu, ls1, 2);
        lrow[0] = lrow[0] * al0 + ls0;
        lrow[1] = lrow[1] * al1 + ls1;

#pragma unroll
        for (int nt = 0; nt < 16; nt++) {
            accO[nt][0] *= al0; accO[nt][1] *= al0;
            accO[nt][2] *= al1; accO[nt][3] *= al1;
        }
        __syncwarp();

        const uint32_t* Pu = (const uint32_t*)Ps;
        const uint32_t* Vu = (const uint32_t*)Vs;
#pragma unroll
        for (int ks = 0; ks < 8; ks++) {
            const int k = ks * 8;
            uint32_t a[4];
            a[0] = Pu[(wrow + gID)     * PS_ + k + tig];
            a[1] = Pu[(wrow + gID + 8) * PS_ + k + tig];
            a[2] = Pu[(wrow + gID)     * PS_ + k + tig + 4];
            a[3] = Pu[(wrow + gID + 8) * PS_ + k + tig + 4];
#pragma unroll
            for (int nt = 0; nt < 16; nt++) {
                uint32_t b[2];
                b[0] = Vu[(k + tig)     * VS_ + nt * 8 + gID];
                b[1] = Vu[(k + tig + 4) * VS_ + nt * 8 + gID];
                mma_tf32(accO[nt], a, b);
            }
        }
    }

    float li0 = 1.f / lrow[0];
    float li1 = 1.f / lrow[1];
    int r0 = qb * BQ + wrow + gID;
    int r1 = r0 + 8;
#pragma unroll
    for (int nt = 0; nt < 16; nt++) {
        int c = h * HD + nt * 8 + 2 * tig;
        *(float2*)(ctx + (size_t)r0 * DOUT + c) =
            make_float2(accO[nt][0] * li0, accO[nt][1] * li0);
        *(float2*)(ctx + (size_t)r1 * DOUT + c) =
            make_float2(accO[nt][2] * li1, accO[nt][3] * li1);
    }
}

// ---------------------------------------------------------------------------
// Launch
// ---------------------------------------------------------------------------
extern "C" void kernel_launch(void* const* d_in, const int* in_sizes, int n_in,
                              void* d_out, int out_size)
{
    const float* x    = (const float*)d_in[0];
    const float* cosT = (const float*)d_in[1];
    const float* sinT = (const float*)d_in[2];
    const float* Wq   = (const float*)d_in[3];
    const float* Wk   = (const float*)d_in[4];
    const float* Wv   = (const float*)d_in[5];
    const float* Wo   = (const float*)d_in[6];
    float* out = (float*)d_out;

    float *Qp, *Kp, *Vp, *Cp;
    cudaGetSymbolAddress((void**)&Qp, g_Q);
    cudaGetSymbolAddress((void**)&Kp, g_K);
    cudaGetSymbolAddress((void**)&Vp, g_V);
    cudaGetSymbolAddress((void**)&Cp, g_ctx);

    cudaFuncSetAttribute(gemm_qkv, cudaFuncAttributeMaxDynamicSharedMemorySize, GEMM_SMEM);
    cudaFuncSetAttribute(gemm_nt,  cudaFuncAttributeMaxDynamicSharedMemorySize, GEMM_SMEM);

    const int ATTN_SMEM = (BQ * QKS + BKV * QKS + BKV * VS_ + BQ * PS_) * (int)sizeof(float);
    cudaFuncSetAttribute(attn_mma, cudaFuncAttributeMaxDynamicSharedMemorySize, ATTN_SMEM);

    // Fused QKV projection (48 n-blocks: 32 Q, 8 K, 8 V)
    gemm_qkv<<<dim3(48, SEQ / 128), 128, GEMM_SMEM>>>(x, Wq, Wk, Wv, Qp, Kp, Vp);

    // RoPE on Q and K
    {
        int totQ = SEQ * NH * 64;
        rope_kernel<<<(totQ + 255) / 256, 256>>>(Qp, cosT, sinT, NH);
        int totK = SEQ * NKV * 64;
        rope_kernel<<<(totK + 255) / 256, 256>>>(Kp, cosT, sinT, NKV);
    }

    // Tensor-core flash attention
    attn_mma<<<dim3(SEQ / BQ, NH), 128, ATTN_SMEM>>>(Qp, Kp, Vp, Cp);

    // Output projection
    gemm_nt<<<dim3(DOUT / 128, SEQ / 128), 128, GEMM_SMEM>>>(Cp, Wo, out, DIN, DOUT);
}